// round 12
// baseline (speedup 1.0000x reference)
#include <cuda_runtime.h>
#include <cuda_bf16.h>
#include <math.h>
#include <stdint.h>

#define DT 0.01f
#define N_STEPS 20
#define PMIN (-8.0f)
#define TAB_N 512
#define TAB_STEP (16.0f / (float)TAB_N)
#define TAB_INV_STEP ((float)TAB_N / 16.0f)

// ---------------- precomputed globals (one parallel prep kernel) ----------------
// main B fragments: uint4 = {hi_reg0, hi_reg1, lo_reg0, lo_reg1}; idx = (kt*8+nt)*32+lane
__device__ __align__(16) uint4 g_Bc[2048];
// scene_w preact B fragments (K=16, one k-tile): idx = nt*32+lane
__device__ __align__(16) uint4 g_Bs[256];
__device__ __align__(16) float2 g_tab[TAB_N];   // p -> F20(sigmoid(p)) {val, delta}
__device__ __align__(16) float g_c[64];         // fused bias

// ---------------- helpers ----------------
__device__ __forceinline__ uint32_t smem_u32(const void* p) {
    uint32_t a;
    asm("{ .reg .u64 t; cvta.to.shared.u64 t, %1; cvt.u32.u64 %0, t; }"
        : "=r"(a) : "l"(p));
    return a;
}
__device__ __forceinline__ void split2(float v0, float v1, uint32_t& hi, uint32_t& lo) {
    __nv_bfloat16 h0 = __float2bfloat16(v0);
    __nv_bfloat16 h1 = __float2bfloat16(v1);
    float r0 = v0 - __bfloat162float(h0);
    float r1 = v1 - __bfloat162float(h1);
    __nv_bfloat16 l0 = __float2bfloat16(r0);
    __nv_bfloat16 l1 = __float2bfloat16(r1);
    hi = ((uint32_t)__bfloat16_as_ushort(h1) << 16) | (uint32_t)__bfloat16_as_ushort(h0);
    lo = ((uint32_t)__bfloat16_as_ushort(l1) << 16) | (uint32_t)__bfloat16_as_ushort(l0);
}
__device__ __forceinline__ void mma16816(float* d, const uint32_t* a, uint32_t b0, uint32_t b1) {
    asm("mma.sync.aligned.m16n8k16.row.col.f32.bf16.bf16.f32 "
        "{%0,%1,%2,%3}, {%4,%5,%6,%7}, {%8,%9}, {%0,%1,%2,%3};"
        : "+f"(d[0]), "+f"(d[1]), "+f"(d[2]), "+f"(d[3])
        : "r"(a[0]), "r"(a[1]), "r"(a[2]), "r"(a[3]), "r"(b0), "r"(b1));
}
__device__ __forceinline__ void ldmx4(uint32_t* r, uint32_t saddr) {
    asm volatile("ldmatrix.sync.aligned.m8n8.x4.shared.b16 {%0,%1,%2,%3}, [%4];"
                 : "=r"(r[0]), "=r"(r[1]), "=r"(r[2]), "=r"(r[3]) : "r"(saddr));
}
__device__ __forceinline__ float evolve(float p) {
    float a = 1.0f / (1.0f + expf(-p));
#pragma unroll
    for (int t = 0; t < N_STEPS; t++) {
        float t2 = 1.0f - a * a;
        a = fmaf(DT, a * t2, a);
    }
    return a;
}

// ---------------- prep kernel (all tasks parallel) ----------------
__device__ __forceinline__ float fetchB(int k, int n, const float* qw, const float* w1) {
    if (k < 64) return w1[(24 + k) * 64 + n];
    if (k < 124) {
        int i = k - 64;
        float acc = 0.0f;
#pragma unroll 8
        for (int m = 0; m < 64; m++)
            acc = fmaf(qw[i * 64 + m], w1[(88 + m) * 64 + n], acc);
        return acc;
    }
    return 0.0f;
}

__global__ void prep_kernel(const float* __restrict__ qw,   // (60,64)
                            const float* __restrict__ qb,   // (64,)
                            const float* __restrict__ w1,   // (152,64)
                            const float* __restrict__ b1,   // (64,)
                            const float* __restrict__ sw)   // scene_w (16,64)
{
    int bid = blockIdx.x, tid = threadIdx.x;
    if (bid < 8) {
        int idx = bid * 256 + tid;
        int lane = idx & 31;
        int nt = (idx >> 5) & 7;
        int kt = idx >> 8;
        int g = lane >> 2, t = lane & 3;
        int n = nt * 8 + g;
        int kb = kt * 16 + 2 * t;
        float v0 = fetchB(kb, n, qw, w1);
        float v1 = fetchB(kb + 1, n, qw, w1);
        float v2 = fetchB(kb + 8, n, qw, w1);
        float v3 = fetchB(kb + 9, n, qw, w1);
        uint32_t h0, l0, h1, l1;
        split2(v0, v1, h0, l0);
        split2(v2, v3, h1, l1);
        g_Bc[idx] = make_uint4(h0, h1, l0, l1);
    } else if (bid == 8) {
        if (tid < 256) {
            int lane = tid & 31;
            int nt = tid >> 5;
            int g = lane >> 2, t = lane & 3;
            int n = nt * 8 + g;
            int kb = 2 * t;
            float v0 = sw[kb * 64 + n];
            float v1 = sw[(kb + 1) * 64 + n];
            float v2 = sw[(kb + 8) * 64 + n];
            float v3 = sw[(kb + 9) * 64 + n];
            uint32_t h0, l0, h1, l1;
            split2(v0, v1, h0, l0);
            split2(v2, v3, h1, l1);
            g_Bs[tid] = make_uint4(h0, h1, l0, l1);
        }
    } else if (bid == 9) {
        __shared__ float v[TAB_N + 1];
        for (int i = tid; i <= TAB_N; i += 256)
            v[i] = evolve(PMIN + (float)i * TAB_STEP);
        __syncthreads();
        for (int i = tid; i < TAB_N; i += 256)
            g_tab[i] = make_float2(v[i], v[i + 1] - v[i]);
    } else {
        if (tid < 64) {
            int k = tid;
            float acc = b1[k];
            for (int r = 0; r < 24; r++) acc += w1[r * 64 + k];  // delta/theta amps == 1
            for (int m = 0; m < 64; m++)
                acc = fmaf(qb[m], w1[(88 + m) * 64 + k], acc);
            g_c[k] = acc;
        }
    }
}

// ---------------- main kernel ----------------
// smem (u32): table [0,1024); scene_b [1024,1088);
//   per group (2 groups): Qhi 1056, Qlo 1056, Ghi 1056, Glo 1056 = 4224
//   s16 tiles: 2 x 512 at O_S16
//   D staging overlays A regions after syncthreads: per warp 2176 at O_A+wid*2176
#define O_TAB 0
#define O_SB 1024
#define O_A 1088
#define GROUP_A 4224
#define O_S16 (O_A + 2 * GROUP_A)       // 9536
#define SMEM_U32 (O_S16 + 2 * 512)      // 10560 u32 = 42.24 KB

// one k-tile of MMAs for an m32 tile; A row stride 128B (interleaved-chunk layout,
// lo tile at a_hi + 4224B)
__device__ __forceinline__ void do_kt(float (*d)[8][4], int kt, uint32_t a_hi, uint32_t a_lo,
                                      int lane) {
    uint4 bv[8];
#pragma unroll
    for (int nt = 0; nt < 8; nt++) bv[nt] = __ldg(&g_Bc[(kt * 8 + nt) * 32 + lane]);
    const int rl = lane & 15;
    const int ch = kt * 2 + ((lane >> 4) & 1);
    const uint32_t off = (uint32_t)rl * 128u + (uint32_t)(((ch & 7) ^ (rl & 7)) * 16) +
                         (uint32_t)((ch >> 3) * 128);  // chunks 8-15 sit at +128B in-row
    uint32_t ah[2][4], al[2][4];
    ldmx4(ah[0], a_hi + off);
    ldmx4(ah[1], a_hi + 2048u + off);
    ldmx4(al[0], a_lo + off);
    ldmx4(al[1], a_lo + 2048u + off);
#pragma unroll
    for (int mt = 0; mt < 2; mt++)
#pragma unroll
        for (int nt = 0; nt < 8; nt++) {
            mma16816(d[mt][nt], ah[mt], bv[nt].x, bv[nt].y);
            mma16816(d[mt][nt], ah[mt], bv[nt].z, bv[nt].w);
            mma16816(d[mt][nt], al[mt], bv[nt].x, bv[nt].y);
        }
}

__global__ __launch_bounds__(128, 4) void dtg_kernel(
    const float* __restrict__ scene,    // (B,8,16)
    const float* __restrict__ query,    // (B,60)
    const float* __restrict__ scene_b,  // (64,)
    const float* __restrict__ w2,       // (64,2)
    const float* __restrict__ b2,       // (2,)
    float* __restrict__ out,            // (B,2)
    int B)
{
    __shared__ uint32_t sm32[SMEM_U32];

    const int tid = threadIdx.x;
    const int lane = tid & 31;
    const int wid = tid >> 5;
    const int g = wid >> 1;
    const int isq = !(wid & 1);         // even warp = query (kt 4-7)
    const int rsw = lane & 7;
    const int fg = lane >> 2;
    const int ft = lane & 3;

    const int s0 = blockIdx.x * 64;
    const int s = s0 + g * 32 + lane;
    const int s_eff = (s < B) ? s : (B - 1);

    // ---- light startup ----
    {
        const float4* tg = (const float4*)g_tab;
        float4* ts = (float4*)(sm32 + O_TAB);
        ts[tid] = tg[tid];
        ts[tid + 128] = tg[tid + 128];
        if (tid < 64) ((float*)(sm32 + O_SB))[tid] = scene_b[tid];
    }
    __syncthreads();

    uint32_t* Qp = sm32 + O_A + g * GROUP_A;          // Qhi 1056, Qlo +1056
    uint32_t* Gp = Qp + 2112;                          // Ghi 1056, Glo +1056

    float d[2][8][4];
#pragma unroll
    for (int mt = 0; mt < 2; mt++)
#pragma unroll
        for (int nt = 0; nt < 8; nt++)
#pragma unroll
            for (int e = 0; e < 4; e++) d[mt][nt][e] = 0.0f;

    if (isq) {
        // ============== QUERY warp: stage Q tile, MMA kt 4-7 ==============
        const float4* qg = (const float4*)(query + (size_t)s_eff * 60);
#pragma unroll
        for (int cc = 0; cc < 8; cc++) {
            float4 va = qg[2 * cc];
            float4 vb = (cc < 7) ? qg[2 * cc + 1] : make_float4(0.f, 0.f, 0.f, 0.f);
            uint32_t hv[4], lv[4];
            split2(va.x, va.y, hv[0], lv[0]);
            split2(va.z, va.w, hv[1], lv[1]);
            split2(vb.x, vb.y, hv[2], lv[2]);
            split2(vb.z, vb.w, hv[3], lv[3]);
            // chunk index 8+cc: in-row offset = 128B + swizzled 16B slot
            int phys = (cc ^ rsw);
            *(uint4*)(Qp + lane * 32 + 32 + phys * 4) = make_uint4(hv[0], hv[1], hv[2], hv[3]);
            *(uint4*)(Qp + 1056 + lane * 32 + 32 + phys * 4) =
                make_uint4(lv[0], lv[1], lv[2], lv[3]);
        }
        __syncwarp();
        const uint32_t a_hi = smem_u32(Qp);
        const uint32_t a_lo = a_hi + 4224u;
#pragma unroll
        for (int ktl = 0; ktl < 4; ktl++) do_kt(&d[0], 4 + ktl, a_hi, a_lo, lane);
    } else {
        // ============== GAMMA warp: scene -> preact-MMA -> lookup -> MMA kt 0-3 ====
        uint32_t* s16p = sm32 + O_S16 + g * 512;
        const uint32_t s16sh = smem_u32(s16p);
        // scene load + mean
        float s16[16];
        {
            const float4* sp = (const float4*)(scene + (size_t)s_eff * 128);
            float4 a0 = sp[0], a1 = sp[1], a2 = sp[2], a3 = sp[3];
#pragma unroll
            for (int n = 1; n < 8; n++) {
                float4 v0 = sp[n * 4 + 0], v1 = sp[n * 4 + 1];
                float4 v2 = sp[n * 4 + 2], v3 = sp[n * 4 + 3];
                a0.x += v0.x; a0.y += v0.y; a0.z += v0.z; a0.w += v0.w;
                a1.x += v1.x; a1.y += v1.y; a1.z += v1.z; a1.w += v1.w;
                a2.x += v2.x; a2.y += v2.y; a2.z += v2.z; a2.w += v2.w;
                a3.x += v3.x; a3.y += v3.y; a3.z += v3.z; a3.w += v3.w;
            }
            const float q8 = 0.125f;
            s16[0] = a0.x * q8;  s16[1] = a0.y * q8;  s16[2] = a0.z * q8;  s16[3] = a0.w * q8;
            s16[4] = a1.x * q8;  s16[5] = a1.y * q8;  s16[6] = a1.z * q8;  s16[7] = a1.w * q8;
            s16[8] = a2.x * q8;  s16[9] = a2.y * q8;  s16[10] = a2.z * q8; s16[11] = a2.w * q8;
            s16[12] = a3.x * q8; s16[13] = a3.y * q8; s16[14] = a3.z * q8; s16[15] = a3.w * q8;
        }
        // stage s16 tile (row = lane, 8 u32 stride; hi then lo at +256)
        {
            uint32_t hv[8], lv[8];
#pragma unroll
            for (int u = 0; u < 8; u++) split2(s16[2 * u], s16[2 * u + 1], hv[u], lv[u]);
            *(uint4*)(s16p + lane * 8 + 0) = make_uint4(hv[0], hv[1], hv[2], hv[3]);
            *(uint4*)(s16p + lane * 8 + 4) = make_uint4(hv[4], hv[5], hv[6], hv[7]);
            *(uint4*)(s16p + 256 + lane * 8 + 0) = make_uint4(lv[0], lv[1], lv[2], lv[3]);
            *(uint4*)(s16p + 256 + lane * 8 + 4) = make_uint4(lv[4], lv[5], lv[6], lv[7]);
        }
        __syncwarp();
        // preact-MMA + lookups + scatter into G (chunks 0-7)
        {
            const float2* sTab = (const float2*)(sm32 + O_TAB);
            const float* sb = (const float*)(sm32 + O_SB);
            const int rl = lane & 15;
            const int lk = (lane >> 4) & 1;
            const uint32_t s16off = (uint32_t)rl * 32u + (uint32_t)lk * 16u;
#pragma unroll
            for (int mt = 0; mt < 2; mt++) {
                uint32_t ah[4], al[4];
                ldmx4(ah, s16sh + (uint32_t)(mt * 16) * 32u + s16off);
                ldmx4(al, s16sh + 1024u + (uint32_t)(mt * 16) * 32u + s16off);
                float dp[8][4];
#pragma unroll
                for (int nt = 0; nt < 8; nt++) {
#pragma unroll
                    for (int e = 0; e < 4; e++) dp[nt][e] = 0.0f;
                    uint4 bs = __ldg(&g_Bs[nt * 32 + lane]);
                    mma16816(dp[nt], ah, bs.x, bs.y);
                    mma16816(dp[nt], ah, bs.z, bs.w);
                    mma16816(dp[nt], al, bs.x, bs.y);
                }
#pragma unroll
                for (int nt = 0; nt < 8; nt++) {
                    int j0 = nt * 8 + 2 * ft;
                    float sb0 = sb[j0], sb1 = sb[j0 + 1];
#pragma unroll
                    for (int rh = 0; rh < 2; rh++) {
                        float p0 = dp[nt][2 * rh + 0] + sb0;
                        float p1 = dp[nt][2 * rh + 1] + sb1;
                        float xf0 = (p0 - PMIN) * TAB_INV_STEP;
                        float xf1 = (p1 - PMIN) * TAB_INV_STEP;
                        int ix0 = min(max(__float2int_rd(xf0), 0), TAB_N - 1);
                        int ix1 = min(max(__float2int_rd(xf1), 0), TAB_N - 1);
                        float2 tv0 = sTab[ix0];
                        float2 tv1 = sTab[ix1];
                        float ag0 = fmaf(xf0 - (float)ix0, tv0.y, tv0.x);
                        float ag1 = fmaf(xf1 - (float)ix1, tv1.y, tv1.x);
                        uint32_t hv, lv;
                        split2(ag0, ag1, hv, lv);
                        int rr = mt * 16 + fg + 8 * rh;
                        int phys = nt ^ (rr & 7);
                        Gp[rr * 32 + phys * 4 + ft] = hv;
                        Gp[1056 + rr * 32 + phys * 4 + ft] = lv;
                    }
                }
            }
        }
        __syncwarp();
        const uint32_t a_hi = smem_u32(Gp);
        const uint32_t a_lo = a_hi + 4224u;
#pragma unroll
        for (int ktl = 0; ktl < 4; ktl++) do_kt(&d[0], ktl, a_hi, a_lo, lane);
    }

    // ---- all MMAs done; overlay D staging (per warp, stride 68) ----
    __syncthreads();
    {
        float* dbuf = (float*)(sm32 + O_A) + wid * 2176;
#pragma unroll
        for (int mt = 0; mt < 2; mt++)
#pragma unroll
            for (int nt = 0; nt < 8; nt++) {
                int r0 = mt * 16 + fg;
                *(float2*)(dbuf + r0 * 68 + nt * 8 + 2 * ft) =
                    make_float2(d[mt][nt][0], d[mt][nt][1]);
                *(float2*)(dbuf + (r0 + 8) * 68 + nt * 8 + 2 * ft) =
                    make_float2(d[mt][nt][2], d[mt][nt][3]);
            }
    }
    __syncthreads();

    // ---- epilogue: 64 threads, one sample each; h = D_A + D_B + c ----
    if (tid < 64) {
        const int eg = tid >> 5;
        const int er = tid & 31;
        const float* dq = (const float*)(sm32 + O_A) + (2 * eg) * 2176 + er * 68;
        const float* dg = (const float*)(sm32 + O_A) + (2 * eg + 1) * 2176 + er * 68;
        const float2* w2p = (const float2*)w2;
        float l0 = __ldg(b2), l1 = __ldg(b2 + 1);
#pragma unroll
        for (int c = 0; c < 16; c++) {
            float4 hq = *(const float4*)(dq + 4 * c);
            float4 hg = *(const float4*)(dg + 4 * c);
            float h0 = fmaxf(hq.x + hg.x + __ldg(g_c + 4 * c + 0), 0.0f);
            float h1 = fmaxf(hq.y + hg.y + __ldg(g_c + 4 * c + 1), 0.0f);
            float h2 = fmaxf(hq.z + hg.z + __ldg(g_c + 4 * c + 2), 0.0f);
            float h3 = fmaxf(hq.w + hg.w + __ldg(g_c + 4 * c + 3), 0.0f);
            float2 w0 = __ldg(w2p + 4 * c + 0), w1v = __ldg(w2p + 4 * c + 1);
            float2 w2v = __ldg(w2p + 4 * c + 2), w3v = __ldg(w2p + 4 * c + 3);
            l0 = fmaf(h0, w0.x, l0);
            l1 = fmaf(h0, w0.y, l1);
            l0 = fmaf(h1, w1v.x, l0);
            l1 = fmaf(h1, w1v.y, l1);
            l0 = fmaf(h2, w2v.x, l0);
            l1 = fmaf(h2, w2v.y, l1);
            l0 = fmaf(h3, w3v.x, l0);
            l1 = fmaf(h3, w3v.y, l1);
        }
        float mx = fmaxf(l0, l1);
        float lse = mx + log1pf(__expf(-fabsf(l0 - l1)));
        int so = s0 + tid;
        if (so < B) ((float2*)out)[so] = make_float2(l0 - lse, l1 - lse);
    }
}

extern "C" void kernel_launch(void* const* d_in, const int* in_sizes, int n_in,
                              void* d_out, int out_size) {
    const float* scene = (const float*)d_in[0];    // (B,8,16)
    const float* query = (const float*)d_in[1];    // (B,60)
    // d_in[2..7]: phases/freqs — unused (amplitude ODE is phase-free; delta/theta
    // amplitudes start at the fixed point 1.0 and stay there)
    const float* scene_w = (const float*)d_in[8];  // (16,64)
    const float* scene_b = (const float*)d_in[9];  // (64,)
    const float* query_w = (const float*)d_in[10]; // (60,64)
    const float* query_b = (const float*)d_in[11]; // (64,)
    const float* ro_w1 = (const float*)d_in[12];   // (152,64)
    const float* ro_b1 = (const float*)d_in[13];   // (64,)
    const float* ro_w2 = (const float*)d_in[14];   // (64,2)
    const float* ro_b2 = (const float*)d_in[15];   // (2,)
    float* out = (float*)d_out;

    int B = in_sizes[0] / 128;

    prep_kernel<<<11, 256>>>(query_w, query_b, ro_w1, ro_b1, scene_w);
    int grid = (B + 63) / 64;
    dtg_kernel<<<grid, 128>>>(scene, query, scene_b, ro_w2, ro_b2, out, B);
}

// round 13
// speedup vs baseline: 1.0934x; 1.0934x over previous
#include <cuda_runtime.h>
#include <cuda_bf16.h>
#include <math.h>
#include <stdint.h>

#define DT 0.01f
#define N_STEPS 20
#define PMIN (-8.0f)
#define TAB_N 512
#define TAB_STEP (16.0f / (float)TAB_N)
#define TAB_INV_STEP ((float)TAB_N / 16.0f)

// ---------------- precomputed globals (one parallel prep kernel) ----------------
// main B fragments: uint4 = {hi_reg0, hi_reg1, lo_reg0, lo_reg1}; idx = (kt*8+nt)*32+lane
__device__ __align__(16) uint4 g_Bc[2048];
// scene_w preact B fragments (K=16, one k-tile): idx = nt*32+lane
__device__ __align__(16) uint4 g_Bs[256];
__device__ __align__(16) float2 g_tab[TAB_N];   // p -> F20(sigmoid(p)) {val, delta}
__device__ __align__(16) float g_c[64];         // fused bias

// ---------------- helpers ----------------
__device__ __forceinline__ uint32_t smem_u32(const void* p) {
    uint32_t a;
    asm("{ .reg .u64 t; cvta.to.shared.u64 t, %1; cvt.u32.u64 %0, t; }"
        : "=r"(a) : "l"(p));
    return a;
}
__device__ __forceinline__ void split2(float v0, float v1, uint32_t& hi, uint32_t& lo) {
    __nv_bfloat16 h0 = __float2bfloat16(v0);
    __nv_bfloat16 h1 = __float2bfloat16(v1);
    float r0 = v0 - __bfloat162float(h0);
    float r1 = v1 - __bfloat162float(h1);
    __nv_bfloat16 l0 = __float2bfloat16(r0);
    __nv_bfloat16 l1 = __float2bfloat16(r1);
    hi = ((uint32_t)__bfloat16_as_ushort(h1) << 16) | (uint32_t)__bfloat16_as_ushort(h0);
    lo = ((uint32_t)__bfloat16_as_ushort(l1) << 16) | (uint32_t)__bfloat16_as_ushort(l0);
}
__device__ __forceinline__ void mma16816(float* d, const uint32_t* a, uint32_t b0, uint32_t b1) {
    asm("mma.sync.aligned.m16n8k16.row.col.f32.bf16.bf16.f32 "
        "{%0,%1,%2,%3}, {%4,%5,%6,%7}, {%8,%9}, {%0,%1,%2,%3};"
        : "+f"(d[0]), "+f"(d[1]), "+f"(d[2]), "+f"(d[3])
        : "r"(a[0]), "r"(a[1]), "r"(a[2]), "r"(a[3]), "r"(b0), "r"(b1));
}
__device__ __forceinline__ void ldmx4(uint32_t* r, uint32_t saddr) {
    asm volatile("ldmatrix.sync.aligned.m8n8.x4.shared.b16 {%0,%1,%2,%3}, [%4];"
                 : "=r"(r[0]), "=r"(r[1]), "=r"(r[2]), "=r"(r[3]) : "r"(saddr));
}
__device__ __forceinline__ float evolve(float p) {
    float a = 1.0f / (1.0f + expf(-p));
#pragma unroll
    for (int t = 0; t < N_STEPS; t++) {
        float t2 = 1.0f - a * a;
        a = fmaf(DT, a * t2, a);
    }
    return a;
}
#define BARS(id, n) asm volatile("bar.sync %0, %1;" :: "r"(id), "r"(n) : "memory")

// ---------------- prep kernel (all tasks parallel) ----------------
__device__ __forceinline__ float fetchB(int k, int n, const float* qw, const float* w1) {
    if (k < 64) return w1[(24 + k) * 64 + n];
    if (k < 124) {
        int i = k - 64;
        float acc = 0.0f;
#pragma unroll 8
        for (int m = 0; m < 64; m++)
            acc = fmaf(qw[i * 64 + m], w1[(88 + m) * 64 + n], acc);
        return acc;
    }
    return 0.0f;
}

__global__ void prep_kernel(const float* __restrict__ qw,   // (60,64)
                            const float* __restrict__ qb,   // (64,)
                            const float* __restrict__ w1,   // (152,64)
                            const float* __restrict__ b1,   // (64,)
                            const float* __restrict__ sw)   // scene_w (16,64)
{
    int bid = blockIdx.x, tid = threadIdx.x;
    if (bid < 8) {
        int idx = bid * 256 + tid;
        int lane = idx & 31;
        int nt = (idx >> 5) & 7;
        int kt = idx >> 8;
        int g = lane >> 2, t = lane & 3;
        int n = nt * 8 + g;
        int kb = kt * 16 + 2 * t;
        float v0 = fetchB(kb, n, qw, w1);
        float v1 = fetchB(kb + 1, n, qw, w1);
        float v2 = fetchB(kb + 8, n, qw, w1);
        float v3 = fetchB(kb + 9, n, qw, w1);
        uint32_t h0, l0, h1, l1;
        split2(v0, v1, h0, l0);
        split2(v2, v3, h1, l1);
        g_Bc[idx] = make_uint4(h0, h1, l0, l1);
    } else if (bid == 8) {
        if (tid < 256) {
            int lane = tid & 31;
            int nt = tid >> 5;
            int g = lane >> 2, t = lane & 3;
            int n = nt * 8 + g;
            int kb = 2 * t;
            float v0 = sw[kb * 64 + n];
            float v1 = sw[(kb + 1) * 64 + n];
            float v2 = sw[(kb + 8) * 64 + n];
            float v3 = sw[(kb + 9) * 64 + n];
            uint32_t h0, l0, h1, l1;
            split2(v0, v1, h0, l0);
            split2(v2, v3, h1, l1);
            g_Bs[tid] = make_uint4(h0, h1, l0, l1);
        }
    } else if (bid == 9) {
        __shared__ float v[TAB_N + 1];
        for (int i = tid; i <= TAB_N; i += 256)
            v[i] = evolve(PMIN + (float)i * TAB_STEP);
        __syncthreads();
        for (int i = tid; i < TAB_N; i += 256)
            g_tab[i] = make_float2(v[i], v[i + 1] - v[i]);
    } else {
        if (tid < 64) {
            int k = tid;
            float acc = b1[k];
            for (int r = 0; r < 24; r++) acc += w1[r * 64 + k];  // delta/theta amps == 1
            for (int m = 0; m < 64; m++)
                acc = fmaf(qb[m], w1[(88 + m) * 64 + k], acc);
            g_c[k] = acc;
        }
    }
}

// ---------------- main kernel ----------------
// smem (u32): table [0,1024); scene_b [1024,1088);
//   per group: Qhi 1056, Qlo 1056, Ghi 1056, Glo 1056 = 4224 (2 groups)
//   s16 tiles: 2 x 512 at O_S16
//   D staging overlays A regions after syncthreads: 64 rows x 68 at O_A
#define O_TAB 0
#define O_SB 1024
#define O_A 1088
#define GROUP_A 4224
#define O_S16 (O_A + 2 * GROUP_A)       // 9536
#define SMEM_U32 (O_S16 + 2 * 512)      // 10560 u32 = 42.24 KB

// one k-tile of MMAs for m32 x n32 (this warp's nt half); A row stride 128B,
// chunks 8-15 at +128B in-row; lo tile at a_hi + 4224B
__device__ __forceinline__ void do_kt4(float (*d)[4][4], int kt, int nh, uint32_t a_hi,
                                       uint32_t a_lo, int lane) {
    uint4 bv[4];
#pragma unroll
    for (int ntl = 0; ntl < 4; ntl++)
        bv[ntl] = __ldg(&g_Bc[(kt * 8 + nh * 4 + ntl) * 32 + lane]);
    const int rl = lane & 15;
    const int ch = kt * 2 + ((lane >> 4) & 1);
    const uint32_t off = (uint32_t)rl * 128u + (uint32_t)(((ch & 7) ^ (rl & 7)) * 16) +
                         (uint32_t)((ch >> 3) * 128);
    uint32_t ah[2][4], al[2][4];
    ldmx4(ah[0], a_hi + off);
    ldmx4(ah[1], a_hi + 2048u + off);
    ldmx4(al[0], a_lo + off);
    ldmx4(al[1], a_lo + 2048u + off);
#pragma unroll
    for (int mt = 0; mt < 2; mt++)
#pragma unroll
        for (int ntl = 0; ntl < 4; ntl++) {
            mma16816(d[mt][ntl], ah[mt], bv[ntl].x, bv[ntl].y);
            mma16816(d[mt][ntl], ah[mt], bv[ntl].z, bv[ntl].w);
            mma16816(d[mt][ntl], al[mt], bv[ntl].x, bv[ntl].y);
        }
}

__global__ __launch_bounds__(128, 5) void dtg_kernel(
    const float* __restrict__ scene,    // (B,8,16)
    const float* __restrict__ query,    // (B,60)
    const float* __restrict__ scene_b,  // (64,)
    const float* __restrict__ w2,       // (64,2)
    const float* __restrict__ b2,       // (2,)
    float* __restrict__ out,            // (B,2)
    int B)
{
    __shared__ uint32_t sm32[SMEM_U32];

    const int tid = threadIdx.x;
    const int lane = tid & 31;
    const int wid = tid >> 5;
    const int g = wid >> 1;
    const int nh = wid & 1;             // this warp's n-half (0: nt 0-3, 1: nt 4-7)
    const int rsw = lane & 7;
    const int fg = lane >> 2;
    const int ft = lane & 3;

    const int s0 = blockIdx.x * 64;
    const int s = s0 + g * 32 + lane;
    const int s_eff = (s < B) ? s : (B - 1);

    // ---- light startup ----
    {
        const float4* tg = (const float4*)g_tab;
        float4* ts = (float4*)(sm32 + O_TAB);
        ts[tid] = tg[tid];
        ts[tid + 128] = tg[tid + 128];
        if (tid < 64) ((float*)(sm32 + O_SB))[tid] = scene_b[tid];
    }
    __syncthreads();

    uint32_t* Qp = sm32 + O_A + g * GROUP_A;  // Qhi; Qlo +1056; Ghi +2112; Glo +3168
    uint32_t* Gp = Qp + 2112;
    uint32_t* s16p = sm32 + O_S16 + g * 512;
    const uint32_t s16sh = smem_u32(s16p);

    // ---- role-split staging: nh==0 stages scene->s16; nh==1 stages query ----
    if (nh) {
        const float4* qg = (const float4*)(query + (size_t)s_eff * 60);
#pragma unroll
        for (int cc = 0; cc < 8; cc++) {
            float4 va = qg[2 * cc];
            float4 vb = (cc < 7) ? qg[2 * cc + 1] : make_float4(0.f, 0.f, 0.f, 0.f);
            uint32_t hv[4], lv[4];
            split2(va.x, va.y, hv[0], lv[0]);
            split2(va.z, va.w, hv[1], lv[1]);
            split2(vb.x, vb.y, hv[2], lv[2]);
            split2(vb.z, vb.w, hv[3], lv[3]);
            int phys = (cc ^ rsw);
            *(uint4*)(Qp + lane * 32 + 32 + phys * 4) = make_uint4(hv[0], hv[1], hv[2], hv[3]);
            *(uint4*)(Qp + 1056 + lane * 32 + 32 + phys * 4) =
                make_uint4(lv[0], lv[1], lv[2], lv[3]);
        }
    } else {
        float s16[16];
        {
            const float4* sp = (const float4*)(scene + (size_t)s_eff * 128);
            float4 a0 = sp[0], a1 = sp[1], a2 = sp[2], a3 = sp[3];
#pragma unroll
            for (int n = 1; n < 8; n++) {
                float4 v0 = sp[n * 4 + 0], v1 = sp[n * 4 + 1];
                float4 v2 = sp[n * 4 + 2], v3 = sp[n * 4 + 3];
                a0.x += v0.x; a0.y += v0.y; a0.z += v0.z; a0.w += v0.w;
                a1.x += v1.x; a1.y += v1.y; a1.z += v1.z; a1.w += v1.w;
                a2.x += v2.x; a2.y += v2.y; a2.z += v2.z; a2.w += v2.w;
                a3.x += v3.x; a3.y += v3.y; a3.z += v3.z; a3.w += v3.w;
            }
            const float q8 = 0.125f;
            s16[0] = a0.x * q8;  s16[1] = a0.y * q8;  s16[2] = a0.z * q8;  s16[3] = a0.w * q8;
            s16[4] = a1.x * q8;  s16[5] = a1.y * q8;  s16[6] = a1.z * q8;  s16[7] = a1.w * q8;
            s16[8] = a2.x * q8;  s16[9] = a2.y * q8;  s16[10] = a2.z * q8; s16[11] = a2.w * q8;
            s16[12] = a3.x * q8; s16[13] = a3.y * q8; s16[14] = a3.z * q8; s16[15] = a3.w * q8;
        }
        uint32_t hv[8], lv[8];
#pragma unroll
        for (int u = 0; u < 8; u++) split2(s16[2 * u], s16[2 * u + 1], hv[u], lv[u]);
        *(uint4*)(s16p + lane * 8 + 0) = make_uint4(hv[0], hv[1], hv[2], hv[3]);
        *(uint4*)(s16p + lane * 8 + 4) = make_uint4(hv[4], hv[5], hv[6], hv[7]);
        *(uint4*)(s16p + 256 + lane * 8 + 0) = make_uint4(lv[0], lv[1], lv[2], lv[3]);
        *(uint4*)(s16p + 256 + lane * 8 + 4) = make_uint4(lv[4], lv[5], lv[6], lv[7]);
    }
    BARS(1 + g, 64);  // Q tile + s16 visible within group

    float d[2][4][4];
#pragma unroll
    for (int mt = 0; mt < 2; mt++)
#pragma unroll
        for (int ntl = 0; ntl < 4; ntl++)
#pragma unroll
            for (int e = 0; e < 4; e++) d[mt][ntl][e] = 0.0f;

    const uint32_t aQ_hi = smem_u32(Qp);
    const uint32_t aQ_lo = aQ_hi + 4224u;
    const uint32_t aG_hi = smem_u32(Gp);
    const uint32_t aG_lo = aG_hi + 4224u;

    // ---- preact (own nt half) interleaved with query k-tiles ----
    {
        const float2* sTab = (const float2*)(sm32 + O_TAB);
        const float* sb = (const float*)(sm32 + O_SB);
        const int rl = lane & 15;
        const int lk = (lane >> 4) & 1;
        const uint32_t s16off = (uint32_t)rl * 32u + (uint32_t)lk * 16u;
#pragma unroll
        for (int mt = 0; mt < 2; mt++) {
            // preact-MMA for this m16 tile, own nt half
            uint32_t ah[4], al[4];
            ldmx4(ah, s16sh + (uint32_t)(mt * 16) * 32u + s16off);
            ldmx4(al, s16sh + 1024u + (uint32_t)(mt * 16) * 32u + s16off);
            float dp[4][4];
#pragma unroll
            for (int ntl = 0; ntl < 4; ntl++) {
#pragma unroll
                for (int e = 0; e < 4; e++) dp[ntl][e] = 0.0f;
                uint4 bs = __ldg(&g_Bs[(nh * 4 + ntl) * 32 + lane]);
                mma16816(dp[ntl], ah, bs.x, bs.y);
                mma16816(dp[ntl], ah, bs.z, bs.w);
                mma16816(dp[ntl], al, bs.x, bs.y);
            }
            // overlap preact latency with 2 query k-tiles
            do_kt4(d, 4 + 2 * mt, nh, aQ_hi, aQ_lo, lane);
            do_kt4(d, 5 + 2 * mt, nh, aQ_hi, aQ_lo, lane);
            // lookups + scatter into G chunks (nt = nh*4+ntl, rows of this mt)
#pragma unroll
            for (int ntl = 0; ntl < 4; ntl++) {
                int nt = nh * 4 + ntl;
                int j0 = nt * 8 + 2 * ft;
                float sb0 = sb[j0], sb1 = sb[j0 + 1];
#pragma unroll
                for (int rh = 0; rh < 2; rh++) {
                    float p0 = dp[ntl][2 * rh + 0] + sb0;
                    float p1 = dp[ntl][2 * rh + 1] + sb1;
                    float xf0 = (p0 - PMIN) * TAB_INV_STEP;
                    float xf1 = (p1 - PMIN) * TAB_INV_STEP;
                    int ix0 = min(max(__float2int_rd(xf0), 0), TAB_N - 1);
                    int ix1 = min(max(__float2int_rd(xf1), 0), TAB_N - 1);
                    float2 tv0 = sTab[ix0];
                    float2 tv1 = sTab[ix1];
                    float ag0 = fmaf(xf0 - (float)ix0, tv0.y, tv0.x);
                    float ag1 = fmaf(xf1 - (float)ix1, tv1.y, tv1.x);
                    uint32_t hv, lv;
                    split2(ag0, ag1, hv, lv);
                    int rr = mt * 16 + fg + 8 * rh;
                    int phys = nt ^ (rr & 7);
                    Gp[rr * 32 + phys * 4 + ft] = hv;
                    Gp[1056 + rr * 32 + phys * 4 + ft] = lv;
                }
            }
        }
    }
    BARS(1 + g, 64);  // G tile complete (both warps' scatters)

    // ---- gamma k-tiles ----
#pragma unroll
    for (int ktl = 0; ktl < 4; ktl++) do_kt4(d, ktl, nh, aG_hi, aG_lo, lane);

    // ---- overlay D staging: each warp owns its m32 x n32 quadrant ----
    __syncthreads();
    {
        float* dbuf = (float*)(sm32 + O_A);
#pragma unroll
        for (int mt = 0; mt < 2; mt++)
#pragma unroll
            for (int ntl = 0; ntl < 4; ntl++) {
                int r0 = g * 32 + mt * 16 + fg;
                int col = nh * 32 + ntl * 8 + 2 * ft;
                *(float2*)(dbuf + r0 * 68 + col) = make_float2(d[mt][ntl][0], d[mt][ntl][1]);
                *(float2*)(dbuf + (r0 + 8) * 68 + col) = make_float2(d[mt][ntl][2], d[mt][ntl][3]);
            }
    }
    __syncthreads();

    // ---- epilogue: 64 threads, one sample each; h = D + c ----
    if (tid < 64) {
        const float* dbuf = (const float*)(sm32 + O_A) + tid * 68;
        const float2* w2p = (const float2*)w2;
        float l0 = __ldg(b2), l1 = __ldg(b2 + 1);
#pragma unroll
        for (int c = 0; c < 16; c++) {
            float4 hv = *(const float4*)(dbuf + 4 * c);
            float h0 = fmaxf(hv.x + __ldg(g_c + 4 * c + 0), 0.0f);
            float h1 = fmaxf(hv.y + __ldg(g_c + 4 * c + 1), 0.0f);
            float h2 = fmaxf(hv.z + __ldg(g_c + 4 * c + 2), 0.0f);
            float h3 = fmaxf(hv.w + __ldg(g_c + 4 * c + 3), 0.0f);
            float2 w0 = __ldg(w2p + 4 * c + 0), w1v = __ldg(w2p + 4 * c + 1);
            float2 w2v = __ldg(w2p + 4 * c + 2), w3v = __ldg(w2p + 4 * c + 3);
            l0 = fmaf(h0, w0.x, l0);
            l1 = fmaf(h0, w0.y, l1);
            l0 = fmaf(h1, w1v.x, l0);
            l1 = fmaf(h1, w1v.y, l1);
            l0 = fmaf(h2, w2v.x, l0);
            l1 = fmaf(h2, w2v.y, l1);
            l0 = fmaf(h3, w3v.x, l0);
            l1 = fmaf(h3, w3v.y, l1);
        }
        float mx = fmaxf(l0, l1);
        float lse = mx + log1pf(__expf(-fabsf(l0 - l1)));
        int so = s0 + tid;
        if (so < B) ((float2*)out)[so] = make_float2(l0 - lse, l1 - lse);
    }
}

extern "C" void kernel_launch(void* const* d_in, const int* in_sizes, int n_in,
                              void* d_out, int out_size) {
    const float* scene = (const float*)d_in[0];    // (B,8,16)
    const float* query = (const float*)d_in[1];    // (B,60)
    // d_in[2..7]: phases/freqs — unused (amplitude ODE is phase-free; delta/theta
    // amplitudes start at the fixed point 1.0 and stay there)
    const float* scene_w = (const float*)d_in[8];  // (16,64)
    const float* scene_b = (const float*)d_in[9];  // (64,)
    const float* query_w = (const float*)d_in[10]; // (60,64)
    const float* query_b = (const float*)d_in[11]; // (64,)
    const float* ro_w1 = (const float*)d_in[12];   // (152,64)
    const float* ro_b1 = (const float*)d_in[13];   // (64,)
    const float* ro_w2 = (const float*)d_in[14];   // (64,2)
    const float* ro_b2 = (const float*)d_in[15];   // (2,)
    float* out = (float*)d_out;

    int B = in_sizes[0] / 128;

    prep_kernel<<<11, 256>>>(query_w, query_b, ro_w1, ro_b1, scene_w);
    int grid = (B + 63) / 64;
    dtg_kernel<<<grid, 128>>>(scene, query, scene_b, ro_w2, ro_b2, out, B);
}